// round 8
// baseline (speedup 1.0000x reference)
#include <cuda_runtime.h>
#include <cuda_bf16.h>
#include <cuda_fp16.h>

#define NMAX 50000
#define DDIM 128
#define EMAX 800000
#define CAP  64
#define OVF_CAP 8192

// ---------------- device-global scratch (allocation-free rule) -------------
__device__ __half g_xjh[NMAX * DDIM]; // lrelu(x0 W2^T + b2), fp16
__device__ float g_e1[NMAX];          // exp(-a1)
__device__ float g_e2[NMAX];          // exp(-a2)
__device__ int   g_idx_is_64;
__device__ int   g_cnt[NMAX];
__device__ int   g_tbl[NMAX * CAP];   // zero-init; always valid node ids
__device__ int   g_ovf_cnt;
__device__ long long g_ovf[OVF_CAP];
__device__ __align__(16) __nv_bfloat16 g_bh[256 * DDIM];
__device__ __align__(16) __nv_bfloat16 g_bl[256 * DDIM];

__device__ __forceinline__ unsigned pack_bf2(float a, float b) {
    __nv_bfloat162 t = __floats2bfloat162_rn(a, b);
    return *reinterpret_cast<unsigned*>(&t);
}
__device__ __forceinline__ unsigned smem_u32(const void* p) {
    unsigned r;
    asm("{ .reg .u64 t; cvta.to.shared.u64 t, %1; cvt.u32.u64 %0, t; }" : "=r"(r) : "l"(p));
    return r;
}
__device__ __forceinline__ void ldm_x4(unsigned* r, unsigned addr) {
    asm volatile("ldmatrix.sync.aligned.m8n8.x4.shared.b16 {%0,%1,%2,%3}, [%4];"
                 : "=r"(r[0]), "=r"(r[1]), "=r"(r[2]), "=r"(r[3]) : "r"(addr));
}
__device__ __forceinline__ void mma16816(float* d, const unsigned* a, const unsigned* b) {
    asm volatile("mma.sync.aligned.m16n8k16.row.col.f32.bf16.bf16.f32 "
                 "{%0,%1,%2,%3}, {%4,%5,%6,%7}, {%8,%9}, {%0,%1,%2,%3};"
                 : "+f"(d[0]), "+f"(d[1]), "+f"(d[2]), "+f"(d[3])
                 : "r"(a[0]), "r"(a[1]), "r"(a[2]), "r"(a[3]), "r"(b[0]), "r"(b[1]));
}
__device__ __forceinline__ void cp16(unsigned saddr, const void* gptr) {
    asm volatile("cp.async.cg.shared.global [%0], [%1], 16;"
                 :: "r"(saddr), "l"(gptr) : "memory");
}

// ---------------------------------------------------------------------------
// Fused prep: dtype probe + zero counters + W split
// ---------------------------------------------------------------------------
__global__ __launch_bounds__(512)
void fused_prep_kernel(const int* __restrict__ ei32,
                       const float* __restrict__ W1, const float* __restrict__ W2, int n)
{
    int id = blockIdx.x * 512 + threadIdx.x;
    if (blockIdx.x == 0 && threadIdx.x < 32) {
        int lane = threadIdx.x;
        int v = ei32[1 + 2 * lane] | ei32[65 + 2 * lane];
        unsigned m = __ballot_sync(0xffffffffu, v == 0);
        if (lane == 0) g_idx_is_64 = (m == 0xffffffffu) ? 1 : 0;
    }
    if (blockIdx.x == 0 && threadIdx.x == 33) g_ovf_cnt = 0;
    if (id < n) g_cnt[id] = 0;
    if (id < 256 * DDIM) {
        int c = id >> 7, k = id & 127;
        float w = (c < DDIM) ? W1[c * DDIM + k] : W2[(c - DDIM) * DDIM + k];
        __nv_bfloat16 h = __float2bfloat16(w);
        g_bh[id] = h;
        g_bl[id] = __float2bfloat16(w - __bfloat162float(h));
    }
}

// ---------------------------------------------------------------------------
// Bucket build: 2 edges per thread, paired loads
// ---------------------------------------------------------------------------
__device__ __forceinline__ void tbl_insert(int src, int dst)
{
    int pos = atomicAdd(&g_cnt[src], 1);
    if (pos < CAP) {
        g_tbl[src * CAP + pos] = dst;
    } else {
        int o = atomicAdd(&g_ovf_cnt, 1);
        if (o < OVF_CAP)
            g_ovf[o] = ((long long)src << 32) | (unsigned int)dst;
    }
}

__global__ __launch_bounds__(256)
void scatter_build_kernel(const void* __restrict__ ei_raw, int E)
{
    int i0 = (blockIdx.x * blockDim.x + threadIdx.x) * 2;
    if (i0 >= E) return;
    int s0, d0, s1, d1;
    bool two = (i0 + 1 < E);
    if (g_idx_is_64) {
        const long long* e = (const long long*)ei_raw;
        if (two) {
            longlong2 sp = *reinterpret_cast<const longlong2*>(e + i0);
            longlong2 dp = *reinterpret_cast<const longlong2*>(e + (long long)E + i0);
            s0 = (int)sp.x; s1 = (int)sp.y;
            d0 = (int)dp.x; d1 = (int)dp.y;
        } else {
            s0 = (int)e[i0]; d0 = (int)e[(long long)E + i0];
            s1 = 0; d1 = 0;
        }
    } else {
        const int* e = (const int*)ei_raw;
        if (two) {
            int2 sp = *reinterpret_cast<const int2*>(e + i0);
            int2 dp = *reinterpret_cast<const int2*>(e + E + i0);
            s0 = sp.x; s1 = sp.y; d0 = dp.x; d1 = dp.y;
        } else {
            s0 = e[i0]; d0 = e[E + i0];
            s1 = 0; d1 = 0;
        }
    }
    tbl_insert(s0, d0);
    if (two) tbl_insert(s1, d1);
}

// ---------------------------------------------------------------------------
// GEMM: split-bf16 HMMA, whole-K single stage; epilogue stores fp16 g_xjh
// ---------------------------------------------------------------------------
#define RS       272
#define SA_H     0
#define SA_LD    34816
#define SB_H     69632
#define SB_LD    69632
#define P_OFF    208896
#define RED_OFF  210944
#define SMEM_TOT 211968

__global__ __launch_bounds__(512, 1)
void gemm_mma_kernel(const float* __restrict__ x0,
                     const float* __restrict__ b1, const float* __restrict__ b2,
                     const float* __restrict__ a1w, const float* __restrict__ a1b,
                     const float* __restrict__ a2w, const float* __restrict__ a2b,
                     int n)
{
    extern __shared__ __align__(16) char sm[];
    const unsigned sb = smem_u32(sm);
    const int tid  = threadIdx.x;
    const int wid  = tid >> 5;
    const int lane = tid & 31;
    const int wr   = wid & 3;
    const int wc   = wid >> 2;
    const int row0 = blockIdx.x * 128;

    float* s_b1  = (float*)(sm + P_OFF);
    float* s_b2  = (float*)(sm + P_OFF + 512);
    float* s_a1w = (float*)(sm + P_OFF + 1024);
    float* s_a2w = (float*)(sm + P_OFF + 1536);
    float* s_r1  = (float*)(sm + RED_OFF);
    float* s_r2  = (float*)(sm + RED_OFF + 512);

    if (tid < 128) {
        s_b1[tid] = b1[tid]; s_b2[tid] = b2[tid];
        s_a1w[tid] = a1w[tid]; s_a2w[tid] = a2w[tid];
        s_r1[tid] = 0.f; s_r2[tid] = 0.f;
    }

    // B stage via cp.async
    {
        const char* srch = (const char*)g_bh;
        const char* srcl = (const char*)g_bl;
#pragma unroll
        for (int j = 0; j < 8; j++) {
            int id  = tid + 512 * j;
            int row = id >> 4;
            int ch  = id & 15;
            unsigned dst = sb + SB_H + row * RS + ch * 16;
            cp16(dst,         srch + row * 256 + ch * 16);
            cp16(dst + SB_LD, srcl + row * 256 + ch * 16);
        }
    }
    asm volatile("cp.async.commit_group;" ::: "memory");

    // A stage: fp32 -> bf16 hi/lo
    {
        int row  = tid >> 2;
        int seg  = tid & 3;
        int grow = row0 + row;
        const float4* xr = reinterpret_cast<const float4*>(x0 + (size_t)grow * DDIM);
#pragma unroll
        for (int g = 0; g < 8; g++) {
            int q = seg * 8 + g;
            float4 v = (grow < n) ? xr[q] : make_float4(0.f, 0.f, 0.f, 0.f);
            __nv_bfloat16 hx = __float2bfloat16(v.x), hy = __float2bfloat16(v.y);
            __nv_bfloat16 hz = __float2bfloat16(v.z), hw = __float2bfloat16(v.w);
            uint2 hv, lv;
            hv.x = pack_bf2(v.x, v.y); hv.y = pack_bf2(v.z, v.w);
            lv.x = pack_bf2(v.x - __bfloat162float(hx), v.y - __bfloat162float(hy));
            lv.y = pack_bf2(v.z - __bfloat162float(hz), v.w - __bfloat162float(hw));
            char* dst = sm + SA_H + row * RS + q * 8;
            *reinterpret_cast<uint2*>(dst)         = hv;
            *reinterpret_cast<uint2*>(dst + SA_LD) = lv;
        }
    }
    asm volatile("cp.async.wait_group 0;" ::: "memory");
    __syncthreads();

    float acc[2][8][4];
#pragma unroll
    for (int i = 0; i < 2; i++)
#pragma unroll
        for (int j = 0; j < 8; j++)
#pragma unroll
            for (int q = 0; q < 4; q++) acc[i][j][q] = 0.f;

#pragma unroll
    for (int ks = 0; ks < 8; ks++) {
        unsigned ah[2][4], al[2][4];
        unsigned abase = sb + SA_H + (wr * 32 + (lane & 15)) * RS
                       + ks * 32 + (lane >> 4) * 16;
#pragma unroll
        for (int mt = 0; mt < 2; mt++) {
            ldm_x4(ah[mt], abase + mt * 16 * RS);
            ldm_x4(al[mt], abase + mt * 16 * RS + SA_LD);
        }
        unsigned bbase = sb + SB_H
                       + (wc * 64 + ((lane >> 4) * 8) + (lane & 7)) * RS
                       + ks * 32 + (((lane >> 3) & 1) * 16);
#pragma unroll
        for (int np = 0; np < 4; np++) {
            unsigned bh[2][2], bl[2][2];
            ldm_x4(&bh[0][0], bbase + np * 16 * RS);
            ldm_x4(&bl[0][0], bbase + np * 16 * RS + SB_LD);
#pragma unroll
            for (int mt = 0; mt < 2; mt++)
#pragma unroll
                for (int j = 0; j < 2; j++) {
                    mma16816(acc[mt][2 * np + j], ah[mt], bh[j]);
                    mma16816(acc[mt][2 * np + j], ah[mt], bl[j]);
                    mma16816(acc[mt][2 * np + j], al[mt], bh[j]);
                }
        }
    }
    __syncthreads();

    const int qlane = lane >> 2;
    const int cpair = lane & 3;
    const int isY2  = (wc >= 2);
    const float* sbias = isY2 ? s_b2 : s_b1;
    const float* saw   = isY2 ? s_a2w : s_a1w;

#pragma unroll
    for (int mt = 0; mt < 2; mt++) {
        int lr0 = wr * 32 + mt * 16 + qlane;
        int lr1 = lr0 + 8;
        int gr0 = row0 + lr0, gr1 = row0 + lr1;
        float pr0 = 0.f, pr1 = 0.f;
#pragma unroll
        for (int nt = 0; nt < 8; nt++) {
            int cb = wc * 64 + nt * 8 + 2 * cpair;
            int c  = isY2 ? (cb - 128) : cb;
            float y00 = acc[mt][nt][0] + sbias[c];
            float y01 = acc[mt][nt][1] + sbias[c + 1];
            float y10 = acc[mt][nt][2] + sbias[c];
            float y11 = acc[mt][nt][3] + sbias[c + 1];
            y00 = (y00 >= 0.f) ? y00 : 0.2f * y00;
            y01 = (y01 >= 0.f) ? y01 : 0.2f * y01;
            y10 = (y10 >= 0.f) ? y10 : 0.2f * y10;
            y11 = (y11 >= 0.f) ? y11 : 0.2f * y11;
            pr0 += y00 * saw[c] + y01 * saw[c + 1];
            pr1 += y10 * saw[c] + y11 * saw[c + 1];
            if (isY2) {
                if (gr0 < n)
                    *reinterpret_cast<__half2*>(&g_xjh[(size_t)gr0 * DDIM + c]) =
                        __floats2half2_rn(y00, y01);
                if (gr1 < n)
                    *reinterpret_cast<__half2*>(&g_xjh[(size_t)gr1 * DDIM + c]) =
                        __floats2half2_rn(y10, y11);
            }
        }
#pragma unroll
        for (int off = 1; off < 4; off <<= 1) {
            pr0 += __shfl_xor_sync(0xffffffffu, pr0, off);
            pr1 += __shfl_xor_sync(0xffffffffu, pr1, off);
        }
        if (cpair == 0) {
            float* red = isY2 ? s_r2 : s_r1;
            atomicAdd(&red[lr0], pr0);
            atomicAdd(&red[lr1], pr1);
        }
    }
    __syncthreads();

    if (tid < 128) {
        int grow = row0 + tid;
        if (grow < n) {
            g_e1[grow] = __expf(-(s_r1[tid] + a1b[0]));
            g_e2[grow] = __expf(-(s_r2[tid] + a2b[0]));
        }
    }
}

// ---------------------------------------------------------------------------
// Gather: one warp per src node, chunk-of-8, fp16 rows (8B per lane per edge)
// ---------------------------------------------------------------------------
__global__ __launch_bounds__(256)
void gather_kernel(const float* __restrict__ x0, float* __restrict__ out, int n)
{
    int gw   = (blockIdx.x * blockDim.x + threadIdx.x) >> 5;
    int lane = threadIdx.x & 31;
    if (gw >= n) return;

    int deg = g_cnt[gw];
    if (deg > CAP) deg = CAP;
    const float e1 = g_e1[gw];
    const int* tbl = g_tbl + (unsigned)gw * CAP;
    const char* xjb = (const char*)g_xjh;
    const unsigned lo = (unsigned)lane * 8;   // byte offset within 256B row

    float4 acc = make_float4(0.f, 0.f, 0.f, 0.f);

    for (int base = 0; base < deg; base += 8) {
        int4 q0 = *reinterpret_cast<const int4*>(tbl + base);
        int4 q1 = *reinterpret_cast<const int4*>(tbl + base + 4);
        unsigned id[8] = {(unsigned)q0.x, (unsigned)q0.y, (unsigned)q0.z, (unsigned)q0.w,
                          (unsigned)q1.x, (unsigned)q1.y, (unsigned)q1.z, (unsigned)q1.w};
        float att[8];
#pragma unroll
        for (int j = 0; j < 8; j++) att[j] = g_e2[id[j]];
#pragma unroll
        for (int j = 0; j < 8; j++)
            att[j] = (base + j < deg)
                   ? __fdividef(1.f, 1.f + e1 * att[j]) : 0.f;
        uint2 v[8];
#pragma unroll
        for (int j = 0; j < 8; j++)
            v[j] = *reinterpret_cast<const uint2*>(xjb + ((size_t)id[j] << 8) + lo);
#pragma unroll
        for (int j = 0; j < 8; j++) {
            float2 f0 = __half22float2(*reinterpret_cast<const __half2*>(&v[j].x));
            float2 f1 = __half22float2(*reinterpret_cast<const __half2*>(&v[j].y));
            acc.x += att[j] * f0.x;
            acc.y += att[j] * f0.y;
            acc.z += att[j] * f1.x;
            acc.w += att[j] * f1.y;
        }
    }

    // lane handles 4 consecutive floats at col lane*4
    float4 r = reinterpret_cast<const float4*>(x0 + (size_t)gw * DDIM)[lane];
    reinterpret_cast<float4*>(out + (size_t)gw * DDIM)[lane] =
        make_float4(r.x + acc.x, r.y + acc.y, r.z + acc.z, r.w + acc.w);
}

__global__ void overflow_kernel(float* __restrict__ out)
{
    int nov = g_ovf_cnt;
    if (nov > OVF_CAP) nov = OVF_CAP;
    int warps = (gridDim.x * blockDim.x) >> 5;
    int gw0   = (blockIdx.x * blockDim.x + threadIdx.x) >> 5;
    int lane  = threadIdx.x & 31;
    for (int i = gw0; i < nov; i += warps) {
        long long p = g_ovf[i];
        int src = (int)(p >> 32);
        int dst = (int)(p & 0xffffffffll);
        float att = __fdividef(1.f, 1.f + g_e1[src] * g_e2[dst]);
        uint2 v = *reinterpret_cast<const uint2*>(
            (const char*)g_xjh + ((size_t)(unsigned)dst << 8) + (unsigned)lane * 8);
        float2 f0 = __half22float2(*reinterpret_cast<const __half2*>(&v.x));
        float2 f1 = __half22float2(*reinterpret_cast<const __half2*>(&v.y));
        float mx = att * f0.x, my = att * f0.y, mz = att * f1.x, mw = att * f1.y;
        float* oaddr = out + (size_t)src * DDIM + lane * 4;
        asm volatile("red.global.add.v4.f32 [%0], {%1, %2, %3, %4};"
                     :: "l"(oaddr), "f"(mx), "f"(my), "f"(mz), "f"(mw)
                     : "memory");
    }
}

// ---------------------------------------------------------------------------
// Launcher
// ---------------------------------------------------------------------------
extern "C" void kernel_launch(void* const* d_in, const int* in_sizes, int n_in,
                              void* d_out, int out_size)
{
    const float* x0  = (const float*)d_in[0];
    const void*  ei  = d_in[2];
    const float* W1  = (const float*)d_in[3];
    const float* b1  = (const float*)d_in[4];
    const float* W2  = (const float*)d_in[5];
    const float* b2  = (const float*)d_in[6];
    const float* a1w = (const float*)d_in[7];
    const float* a1b = (const float*)d_in[8];
    const float* a2w = (const float*)d_in[9];
    const float* a2b = (const float*)d_in[10];
    float* out = (float*)d_out;

    const int n = in_sizes[0] / DDIM;   // 50000
    const int E = in_sizes[2] / 2;      // 800000

    static int cfg_done = 0;
    if (!cfg_done) {
        cudaFuncSetAttribute(gemm_mma_kernel,
                             cudaFuncAttributeMaxDynamicSharedMemorySize, SMEM_TOT);
        cfg_done = 1;
    }

    fused_prep_kernel<<<(n + 511) / 512, 512>>>((const int*)ei, W1, W2, n);
    scatter_build_kernel<<<(E / 2 + 255) / 256, 256>>>(ei, E);

    int gblocks = (n + 127) / 128;
    gemm_mma_kernel<<<gblocks, 512, SMEM_TOT>>>(x0, b1, b2, a1w, a1b, a2w, a2b, n);

    int gthreads = n * 32;
    gather_kernel<<<(gthreads + 255) / 256, 256>>>(x0, out, n);

    overflow_kernel<<<8, 256>>>(out);
}